// round 13
// baseline (speedup 1.0000x reference)
#include <cuda_runtime.h>
#include <cuda_fp16.h>
#include <cstdint>
#include <math.h>

#define Bb 64
#define Nn 512
#define Dd 256
#define Ll 4

// ======================= helpers =======================
__device__ __forceinline__ uint32_t smem_u32(const void* p) {
    uint32_t a;
    asm("{ .reg .u64 t; cvta.to.shared.u64 t, %1; cvt.u32.u64 %0, t; }" : "=r"(a) : "l"(p));
    return a;
}
__device__ __forceinline__ void cp16(uint32_t s, const void* g) {
    asm volatile("cp.async.cg.shared.global [%0], [%1], 16;" :: "r"(s), "l"(g));
}
__device__ __forceinline__ void ldsm4(uint32_t* r, uint32_t addr) {
    asm volatile("ldmatrix.sync.aligned.m8n8.x4.shared.b16 {%0,%1,%2,%3}, [%4];"
        : "=r"(r[0]), "=r"(r[1]), "=r"(r[2]), "=r"(r[3]) : "r"(addr));
}
__device__ __forceinline__ void ldsm4t(uint32_t* r, uint32_t addr) {
    asm volatile("ldmatrix.sync.aligned.m8n8.x4.trans.shared.b16 {%0,%1,%2,%3}, [%4];"
        : "=r"(r[0]), "=r"(r[1]), "=r"(r[2]), "=r"(r[3]) : "r"(addr));
}
__device__ __forceinline__ void mma16816(float* d, const uint32_t* a, const uint32_t* b) {
    asm volatile("mma.sync.aligned.m16n8k16.row.col.f32.f16.f16.f32 "
        "{%0,%1,%2,%3}, {%4,%5,%6,%7}, {%8,%9}, {%0,%1,%2,%3};"
        : "+f"(d[0]), "+f"(d[1]), "+f"(d[2]), "+f"(d[3])
        : "r"(a[0]), "r"(a[1]), "r"(a[2]), "r"(a[3]), "r"(b[0]), "r"(b[1]));
}

// ======================= device globals (scratch) =======================
#define XSZ (Bb * Nn * Dd)
#define ASZ (Bb * Nn * Nn)
__device__ __align__(128) __half g_xh[XSZ];
__device__ __align__(128) __half g_th[XSZ];              // MLP hidden h
__device__ __align__(128) __half g_qh[XSZ];              // q, then t1
__device__ __align__(128) __half g_ah[ASZ], g_al[ASZ];   // attn hi/lo (UNNORMALIZED)
__device__ __align__(128) __half g_wh[13 * Dd * Dd];
__device__ __align__(128) float g_x[XSZ];
__device__ __align__(128) float g_part[Bb * Nn * 4];     // row-sum partials (4 ctaY)

// ======================= generic MMA GEMM (q / attn / attn@x) =======================
// BT=0: C = A[M,K] @ (Bh[Ncols,K])^T ; BT=1: C = A[M,K] @ (Bh[K,Ncols]) (trans-ldsm)
// EPI: 1=bias->h | 2=sigmoid*adj->hl + rowsum partials | 7=rowscale(1/sum part)->h
#define TM 128
#define TN 128
#define RS 80
#define RSB 272
#define MAT_BYTES (128 * RS)            // 10240
#define NSTG 3
#define SMEM_P1 (NSTG * 2 * MAT_BYTES)  // 61440

template<int EPI, int BT>
__global__ void __launch_bounds__(256, 2)
mma_gemm(const __half* __restrict__ Ah, const __half* __restrict__ Bh,
         int K, int ldb, long long sAz, long long sBz,
         __half* __restrict__ Ch, __half* __restrict__ Cl,
         long long sCz, int ldc,
         const float* __restrict__ bias,
         const float* __restrict__ adj, float* __restrict__ part)
{
    extern __shared__ char smch[];
    const uint32_t sb = smem_u32(smch);
    const int tid = threadIdx.x;
    const int wid = tid >> 5;
    const int lane = tid & 31;
    const int z = blockIdx.z;
    const int bm = blockIdx.x * TM;
    const int bn = blockIdx.y * TN;

    Ah += (size_t)z * sAz + (size_t)bm * K;
    if (BT) Bh += (size_t)z * sBz + bn;
    else    Bh += (size_t)z * sBz + (size_t)bn * K;

    const int lr = tid >> 1;
    const int lc = (tid & 1) * 2;
    const uint32_t s_off = (uint32_t)lr * RS + (uint32_t)lc * 16;
    const int lrB = tid >> 3;
    const int lsB = tid & 7;

    auto issue = [&](int kb, int buf) {
        const size_t go = (size_t)lr * K + (size_t)kb * 32 + (size_t)lc * 8;
        const uint32_t s0 = sb + buf * (2 * MAT_BYTES) + s_off;
        cp16(s0,      Ah + go);
        cp16(s0 + 16, Ah + go + 8);
        if (BT) {
            const size_t gob = (size_t)(kb * 32 + lrB) * ldb + (size_t)lsB * 16;
            const uint32_t s0b = sb + buf * (2 * MAT_BYTES) + MAT_BYTES
                               + (uint32_t)lrB * RSB + (uint32_t)lsB * 32;
            cp16(s0b,      Bh + gob);
            cp16(s0b + 16, Bh + gob + 8);
        } else {
            const uint32_t s0b = sb + buf * (2 * MAT_BYTES) + MAT_BYTES + s_off;
            cp16(s0b,      Bh + go);
            cp16(s0b + 16, Bh + go + 8);
        }
    };

    const int KB = K / 32;
    issue(0, 0);
    asm volatile("cp.async.commit_group;" ::: "memory");
    issue(1, 1);
    asm volatile("cp.async.commit_group;" ::: "memory");

    const int wm = (wid & 1) * 64;
    const int wn = (wid >> 1) * 32;

    float acc[4][4][4];
    #pragma unroll
    for (int i = 0; i < 4; i++)
        #pragma unroll
        for (int j = 0; j < 4; j++)
            #pragma unroll
            for (int k = 0; k < 4; k++) acc[i][j][k] = 0.0f;

    const int rr = lane & 15;
    const int csel = lane >> 4;
    const int gB = lane >> 3;
    const int rB = lane & 7;

    int bufC = 0, bufW = 2;
    for (int kb = 0; kb < KB; kb++) {
        asm volatile("cp.async.wait_group 1;" ::: "memory");
        __syncthreads();
        const uint32_t bufb = sb + bufC * (2 * MAT_BYTES);

        if (kb + 2 < KB) issue(kb + 2, bufW);
        asm volatile("cp.async.commit_group;" ::: "memory");

        #pragma unroll
        for (int ks = 0; ks < 2; ks++) {
            const uint32_t coff = (uint32_t)(ks * 2 + csel) * 16;
            uint32_t ah[4][4], bh[4][2];
            const uint32_t abase = bufb + (uint32_t)(wm + rr) * RS + coff;
            #pragma unroll
            for (int mt = 0; mt < 4; mt++)
                ldsm4(ah[mt], abase + mt * (16 * RS));
            if (BT) {
                const uint32_t btb = bufb + MAT_BYTES
                    + (uint32_t)(ks * 16 + (gB & 1) * 8 + rB) * RSB
                    + (uint32_t)(wn + (gB >> 1) * 8) * 2;
                #pragma unroll
                for (int ntt = 0; ntt < 2; ntt++) {
                    uint32_t t4[4];
                    ldsm4t(t4, btb + ntt * 32);
                    bh[2 * ntt][0] = t4[0]; bh[2 * ntt][1] = t4[1];
                    bh[2 * ntt + 1][0] = t4[2]; bh[2 * ntt + 1][1] = t4[3];
                }
            } else {
                const uint32_t bbase = bufb + MAT_BYTES + (uint32_t)(wn + rr) * RS + coff;
                #pragma unroll
                for (int ntt = 0; ntt < 2; ntt++) {
                    uint32_t t4[4];
                    ldsm4(t4, bbase + ntt * (16 * RS));
                    bh[2 * ntt][0] = t4[0]; bh[2 * ntt][1] = t4[2];
                    bh[2 * ntt + 1][0] = t4[1]; bh[2 * ntt + 1][1] = t4[3];
                }
            }
            #pragma unroll
            for (int mt = 0; mt < 4; mt++)
                #pragma unroll
                for (int nt = 0; nt < 4; nt++)
                    mma16816(acc[mt][nt], ah[mt], bh[nt]);
        }
        bufC = (bufC == NSTG - 1) ? 0 : bufC + 1;
        bufW = (bufW == NSTG - 1) ? 0 : bufW + 1;
    }

    // ---- epilogue ----
    const int qrow = lane >> 2;
    const int qcol = (lane & 3) * 2;
    float* redsm = (float*)smch;
    float rsum0[4], rsum1[4];

    #pragma unroll
    for (int mt = 0; mt < 4; mt++) {
        const int r0 = bm + wm + mt * 16 + qrow;
        const int r1 = r0 + 8;
        if (EPI == 2) { rsum0[mt] = 0.0f; rsum1[mt] = 0.0f; }
        #pragma unroll
        for (int nt = 0; nt < 4; nt++) {
            const int col = bn + wn + nt * 8 + qcol;
            float v00 = acc[mt][nt][0], v01 = acc[mt][nt][1];
            float v10 = acc[mt][nt][2], v11 = acc[mt][nt][3];

            if (EPI == 2) {
                const float* a0 = adj + ((size_t)z * Nn + r0) * Nn;
                const float* a1 = adj + ((size_t)z * Nn + r1) * Nn;
                float s00 = 1.0f / (1.0f + __expf(-v00));
                float s01 = 1.0f / (1.0f + __expf(-v01));
                float s10 = 1.0f / (1.0f + __expf(-v10));
                float s11 = 1.0f / (1.0f + __expf(-v11));
                v00 = (col == r0)     ? (s00 + 1e-5f) : s00 * __ldg(a0 + col);
                v01 = (col + 1 == r0) ? (s01 + 1e-5f) : s01 * __ldg(a0 + col + 1);
                v10 = (col == r1)     ? (s10 + 1e-5f) : s10 * __ldg(a1 + col);
                v11 = (col + 1 == r1) ? (s11 + 1e-5f) : s11 * __ldg(a1 + col + 1);
                rsum0[mt] += v00 + v01;
                rsum1[mt] += v10 + v11;
            } else if (EPI == 7) {
                const float4 p0 = *(const float4*)(part + ((size_t)z * Nn + r0) * 4);
                const float4 p1 = *(const float4*)(part + ((size_t)z * Nn + r1) * 4);
                const float inv0 = 1.0f / (p0.x + p0.y + p0.z + p0.w);
                const float inv1 = 1.0f / (p1.x + p1.y + p1.z + p1.w);
                v00 *= inv0; v01 *= inv0; v10 *= inv1; v11 *= inv1;
            } else if (EPI == 1) {
                const float b0v = __ldg(bias + col), b1v = __ldg(bias + col + 1);
                v00 += b0v; v01 += b1v; v10 += b0v; v11 += b1v;
            }

            __half* ch0 = Ch + (size_t)z * sCz + (size_t)r0 * ldc;
            __half* ch1 = Ch + (size_t)z * sCz + (size_t)r1 * ldc;
            const __half h00 = __float2half_rn(v00), h01 = __float2half_rn(v01);
            const __half h10 = __float2half_rn(v10), h11 = __float2half_rn(v11);
            __half2 hp0; hp0.x = h00; hp0.y = h01;
            __half2 hp1; hp1.x = h10; hp1.y = h11;
            *(__half2*)(ch0 + col) = hp0;
            *(__half2*)(ch1 + col) = hp1;
            if (EPI == 2) {
                __half* cl0 = Cl + (size_t)z * sCz + (size_t)r0 * ldc;
                __half* cl1 = Cl + (size_t)z * sCz + (size_t)r1 * ldc;
                __half2 lp0, lp1;
                lp0.x = __float2half_rn(v00 - __half2float(h00));
                lp0.y = __float2half_rn(v01 - __half2float(h01));
                lp1.x = __float2half_rn(v10 - __half2float(h10));
                lp1.y = __float2half_rn(v11 - __half2float(h11));
                *(__half2*)(cl0 + col) = lp0;
                *(__half2*)(cl1 + col) = lp1;
            }
        }
    }

    if (EPI == 2) {
        __syncthreads();
        const int nw = wid >> 1;
        #pragma unroll
        for (int mt = 0; mt < 4; mt++) {
            float s0 = rsum0[mt], s1 = rsum1[mt];
            s0 += __shfl_xor_sync(0xffffffffu, s0, 1);
            s0 += __shfl_xor_sync(0xffffffffu, s0, 2);
            s1 += __shfl_xor_sync(0xffffffffu, s1, 1);
            s1 += __shfl_xor_sync(0xffffffffu, s1, 2);
            if ((lane & 3) == 0) {
                const int rc = wm + mt * 16 + qrow;
                redsm[rc * 4 + nw]       = s0;
                redsm[(rc + 8) * 4 + nw] = s1;
            }
        }
        __syncthreads();
        if (tid < 128) {
            const float s = redsm[tid * 4] + redsm[tid * 4 + 1]
                          + redsm[tid * 4 + 2] + redsm[tid * 4 + 3];
            part[((size_t)z * Nn + bm + tid) * 4 + blockIdx.y] = s;
        }
    }
}

// ======================= fused MLP: lin0 -> lin1 -> next-q / final =======================
// Each CTA: 64 rows x full 256 cols; 3 sequential staged-GEMM phases (K=256).
// Intermediates th / xh via L2-resident globals (CTA-local rows only).
#define PRS 80
#define PA_BYTES (64 * PRS)             // 5120
#define PB_BYTES (256 * PRS)            // 20480
#define PSTG (PA_BYTES + PB_BYTES)      // 25600
#define MLP_SMEM (2 * PSTG)             // 51200

__global__ void __launch_bounds__(256, 2)
mlp3(const __half* __restrict__ t1,
     const __half* __restrict__ W0, const float* __restrict__ b0,
     const __half* __restrict__ W1, const float* __restrict__ b1,
     float* __restrict__ gx, __half* __restrict__ xh, __half* __restrict__ th,
     const __half* __restrict__ W2, const float* __restrict__ b2,
     __half* __restrict__ qout, float* __restrict__ fout, int last)
{
    extern __shared__ char smch[];
    const uint32_t sb = smem_u32(smch);
    const int tid = threadIdx.x;
    const int wid = tid >> 5;
    const int lane = tid & 31;
    const int bm = blockIdx.x * 64;

    const int wm = (wid & 1) * 32;
    const int wn = (wid >> 1) * 64;
    const int rr = lane & 15;
    const int csel = lane >> 4;
    const int qrow = lane >> 2;
    const int qcol = (lane & 3) * 2;

    // A loader: row = tid>>2 (0..63), seg = tid&3 ; B loader: row = tid, 4 segs
    const int ar = tid >> 2, as = tid & 3;

    // phase: epi 4 = relu+bias -> th ; 5 = relu+bias+res -> gx + xh ; 3 = bias -> qout/fout
    auto phase = [&](const __half* Agb, const __half* Bg, int epi,
                     const float* bias) {
        const __half* Ag = Agb + (size_t)bm * 256;
        float acc[2][8][4];
        #pragma unroll
        for (int i = 0; i < 2; i++)
            #pragma unroll
            for (int j = 0; j < 8; j++)
                #pragma unroll
                for (int k = 0; k < 4; k++) acc[i][j][k] = 0.0f;

        auto issue = [&](int kb, int buf) {
            cp16(sb + buf * PSTG + (uint32_t)ar * PRS + (uint32_t)as * 16,
                 Ag + (size_t)ar * 256 + kb * 32 + as * 8);
            #pragma unroll
            for (int i = 0; i < 4; i++)
                cp16(sb + buf * PSTG + PA_BYTES + (uint32_t)tid * PRS + i * 16,
                     Bg + (size_t)tid * 256 + kb * 32 + i * 8);
        };
        issue(0, 0);
        asm volatile("cp.async.commit_group;" ::: "memory");
        issue(1, 1);
        asm volatile("cp.async.commit_group;" ::: "memory");

        for (int kb = 0; kb < 8; kb++) {
            asm volatile("cp.async.wait_group 1;" ::: "memory");
            __syncthreads();
            const uint32_t bufb = sb + (kb & 1) * PSTG;
            #pragma unroll
            for (int ks = 0; ks < 2; ks++) {
                const uint32_t coff = (uint32_t)(ks * 2 + csel) * 16;
                uint32_t a[2][4], b[8][2];
                #pragma unroll
                for (int mt = 0; mt < 2; mt++)
                    ldsm4(a[mt], bufb + (uint32_t)(wm + mt * 16 + rr) * PRS + coff);
                const uint32_t bbase = bufb + PA_BYTES + (uint32_t)(wn + rr) * PRS + coff;
                #pragma unroll
                for (int ntt = 0; ntt < 4; ntt++) {
                    uint32_t t4[4];
                    ldsm4(t4, bbase + ntt * (16 * PRS));
                    b[2 * ntt][0] = t4[0]; b[2 * ntt][1] = t4[2];
                    b[2 * ntt + 1][0] = t4[1]; b[2 * ntt + 1][1] = t4[3];
                }
                #pragma unroll
                for (int mt = 0; mt < 2; mt++)
                    #pragma unroll
                    for (int nt = 0; nt < 8; nt++)
                        mma16816(acc[mt][nt], a[mt], b[nt]);
            }
            __syncthreads();
            if (kb + 2 < 8) issue(kb + 2, kb & 1);
            asm volatile("cp.async.commit_group;" ::: "memory");
        }
        asm volatile("cp.async.wait_group 0;" ::: "memory");

        // epilogue
        #pragma unroll
        for (int mt = 0; mt < 2; mt++) {
            const int r0 = bm + wm + mt * 16 + qrow;
            const int r1 = r0 + 8;
            #pragma unroll
            for (int nt = 0; nt < 8; nt++) {
                const int col = wn + nt * 8 + qcol;
                const float bv0 = __ldg(bias + col), bv1 = __ldg(bias + col + 1);
                float v00 = acc[mt][nt][0] + bv0, v01 = acc[mt][nt][1] + bv1;
                float v10 = acc[mt][nt][2] + bv0, v11 = acc[mt][nt][3] + bv1;
                if (epi == 4 || epi == 5) {
                    v00 = fmaxf(v00, 0.0f); v01 = fmaxf(v01, 0.0f);
                    v10 = fmaxf(v10, 0.0f); v11 = fmaxf(v11, 0.0f);
                }
                if (epi == 4) {
                    __half2 p0, p1;
                    p0.x = __float2half_rn(v00); p0.y = __float2half_rn(v01);
                    p1.x = __float2half_rn(v10); p1.y = __float2half_rn(v11);
                    *(__half2*)(th + (size_t)r0 * 256 + col) = p0;
                    *(__half2*)(th + (size_t)r1 * 256 + col) = p1;
                } else if (epi == 5) {
                    float* cf0 = gx + (size_t)r0 * 256;
                    float* cf1 = gx + (size_t)r1 * 256;
                    v00 += cf0[col]; v01 += cf0[col + 1];
                    v10 += cf1[col]; v11 += cf1[col + 1];
                    float2 q0; q0.x = v00; q0.y = v01;
                    float2 q1; q1.x = v10; q1.y = v11;
                    *(float2*)(cf0 + col) = q0;
                    *(float2*)(cf1 + col) = q1;
                    __half2 p0, p1;
                    p0.x = __float2half_rn(v00); p0.y = __float2half_rn(v01);
                    p1.x = __float2half_rn(v10); p1.y = __float2half_rn(v11);
                    *(__half2*)(xh + (size_t)r0 * 256 + col) = p0;
                    *(__half2*)(xh + (size_t)r1 * 256 + col) = p1;
                } else {            // epi == 3: next-q (fp16) or final (fp32)
                    if (last) {
                        float2 q0; q0.x = v00; q0.y = v01;
                        float2 q1; q1.x = v10; q1.y = v11;
                        *(float2*)(fout + (size_t)r0 * 256 + col) = q0;
                        *(float2*)(fout + (size_t)r1 * 256 + col) = q1;
                    } else {
                        __half2 p0, p1;
                        p0.x = __float2half_rn(v00); p0.y = __float2half_rn(v01);
                        p1.x = __float2half_rn(v10); p1.y = __float2half_rn(v11);
                        *(__half2*)(qout + (size_t)r0 * 256 + col) = p0;
                        *(__half2*)(qout + (size_t)r1 * 256 + col) = p1;
                    }
                }
            }
        }
        __syncthreads();   // epilogue global writes visible CTA-wide before next phase reads
    };

    phase(t1, W0, 4, b0);   // h  = relu(t1 @ W0^T + b0)      -> th
    phase(th, W1, 5, b1);   // x  = relu(h  @ W1^T + b1) + x0 -> gx, xh
    phase(xh, W2, 3, b2);   // q' = x @ W2^T + b2             -> qout (or fout if last)
}

// ======================= small kernels =======================
__global__ void __launch_bounds__(256)
split_copy(const float4* __restrict__ src, float4* __restrict__ dst,
           __half* __restrict__ h, int n4)
{
    const int i = blockIdx.x * blockDim.x + threadIdx.x;
    if (i >= n4) return;
    const float4 v = src[i];
    dst[i] = v;
    __half2 a, b;
    a.x = __float2half_rn(v.x); a.y = __float2half_rn(v.y);
    b.x = __float2half_rn(v.z); b.y = __float2half_rn(v.w);
    *(__half2*)(h + 4 * (size_t)i) = a;
    *(__half2*)(h + 4 * (size_t)i + 2) = b;
}

__global__ void __launch_bounds__(256)
wconv(const float* __restrict__ src, __half* __restrict__ h, int n)
{
    const int i = blockIdx.x * blockDim.x + threadIdx.x;
    if (i < n) h[i] = __float2half_rn(src[i]);
}

// write normalized fp32 attn from unnormalized hi/lo + rowsum partials
__global__ void __launch_bounds__(256)
normout(const __half* __restrict__ h, const __half* __restrict__ l,
        const float* __restrict__ part, float* __restrict__ out)
{
    const size_t row = blockIdx.x;
    const float4 p = *(const float4*)(part + row * 4);
    const float inv = 1.0f / (p.x + p.y + p.z + p.w);
    const int t = threadIdx.x;
    const __half2 hv = *(const __half2*)(h + row * Nn + t * 2);
    const __half2 lv = *(const __half2*)(l + row * Nn + t * 2);
    float2 o;
    o.x = (__half2float(hv.x) + __half2float(lv.x)) * inv;
    o.y = (__half2float(hv.y) + __half2float(lv.y)) * inv;
    *(float2*)(out + row * Nn + t * 2) = o;
}

// ======================= launch =======================
extern "C" void kernel_launch(void* const* d_in, const int* in_sizes, int n_in,
                              void* d_out, int out_size)
{
    const float* x_in  = (const float*)d_in[0];
    const float* adj   = (const float*)d_in[1];
    const float* wA_w  = (const float*)d_in[2];
    const float* wA_b  = (const float*)d_in[3];
    const float* l0_w  = (const float*)d_in[4];
    const float* l0_b  = (const float*)d_in[5];
    const float* l1_w  = (const float*)d_in[6];
    const float* l1_b  = (const float*)d_in[7];
    const float* fin_w = (const float*)d_in[8];
    const float* fin_b = (const float*)d_in[9];

    float* out_x = (float*)d_out;
    float* attls = out_x + (size_t)Bb * Nn * Dd;

    __half *xh, *th, *qh, *ah, *al, *wh;
    float *gx, *gp;
    cudaGetSymbolAddress((void**)&xh, g_xh);
    cudaGetSymbolAddress((void**)&th, g_th);
    cudaGetSymbolAddress((void**)&qh, g_qh);
    cudaGetSymbolAddress((void**)&ah, g_ah); cudaGetSymbolAddress((void**)&al, g_al);
    cudaGetSymbolAddress((void**)&wh, g_wh);
    cudaGetSymbolAddress((void**)&gx, g_x);  cudaGetSymbolAddress((void**)&gp, g_part);

    static cudaStream_t s2 = nullptr;
    static cudaEvent_t evRoot, evW, evF[Ll], evJ[Ll];
    if (s2 == nullptr) {
        cudaStreamCreateWithFlags(&s2, cudaStreamNonBlocking);
        cudaEventCreateWithFlags(&evRoot, cudaEventDisableTiming);
        cudaEventCreateWithFlags(&evW, cudaEventDisableTiming);
        for (int l = 0; l < Ll; l++) {
            cudaEventCreateWithFlags(&evF[l], cudaEventDisableTiming);
            cudaEventCreateWithFlags(&evJ[l], cudaEventDisableTiming);
        }
    }

    cudaFuncSetAttribute(mma_gemm<1,0>, cudaFuncAttributeMaxDynamicSharedMemorySize, SMEM_P1);
    cudaFuncSetAttribute(mma_gemm<2,0>, cudaFuncAttributeMaxDynamicSharedMemorySize, SMEM_P1);
    cudaFuncSetAttribute(mma_gemm<7,1>, cudaFuncAttributeMaxDynamicSharedMemorySize, SMEM_P1);
    cudaFuncSetAttribute(mlp3, cudaFuncAttributeMaxDynamicSharedMemorySize, MLP_SMEM);

    const int WSZ = Dd * Dd;
    const long long sX = (long long)Nn * Dd;
    const long long sA = (long long)Nn * Nn;

    // fork s2 at root: weight converts run concurrently with x split_copy
    cudaEventRecord(evRoot, 0);
    cudaStreamWaitEvent(s2, evRoot, 0);
    wconv<<<(4 * WSZ + 255) / 256, 256, 0, s2>>>(wA_w,  wh,            4 * WSZ);
    wconv<<<(4 * WSZ + 255) / 256, 256, 0, s2>>>(l0_w,  wh + 4 * WSZ,  4 * WSZ);
    wconv<<<(4 * WSZ + 255) / 256, 256, 0, s2>>>(l1_w,  wh + 8 * WSZ,  4 * WSZ);
    wconv<<<(WSZ + 255) / 256, 256, 0, s2>>>(fin_w, wh + 12 * WSZ, WSZ);
    cudaEventRecord(evW, s2);

    {
        const int n4 = XSZ / 4;
        split_copy<<<(n4 + 255) / 256, 256>>>((const float4*)x_in, (float4*)gx, xh, n4);
    }
    cudaStreamWaitEvent(0, evW, 0);

    const int BIGM = Bb * Nn;

    // prologue: q(0) = x @ Wa(0)^T + ba(0)
    mma_gemm<1,0><<<dim3(BIGM / TM, Dd / TN, 1), 256, SMEM_P1>>>(
        xh, wh, Dd, 0, 0, 0, qh, nullptr, 0, Dd, wA_b, nullptr, nullptr);

    for (int l = 0; l < Ll; l++) {
        const float* b0 = l0_b + (size_t)l * Dd;
        const float* b1 = l1_b + (size_t)l * Dd;
        const __half* W0h = wh + (size_t)(4 + l) * WSZ;
        const __half* W1h = wh + (size_t)(8 + l) * WSZ;
        const int last = (l == Ll - 1);
        const __half* W2h = last ? (wh + 12 * WSZ) : (wh + (size_t)(l + 1) * WSZ);
        const float* b2   = last ? fin_b : (wA_b + (size_t)(l + 1) * Dd);
        float* attl = attls + (size_t)l * Bb * Nn * Nn;

        if (l > 0) cudaStreamWaitEvent(0, evJ[l - 1], 0);

        // attn_unnorm = sig(q @ x^T)*adj (+diag) -> ah/al + partials
        mma_gemm<2,0><<<dim3(Nn / TM, Nn / TN, Bb), 256, SMEM_P1>>>(
            qh, xh, Dd, 0, sX, sX, ah, al, sA, Nn, nullptr, adj, gp);

        cudaEventRecord(evF[l], 0);
        cudaStreamWaitEvent(s2, evF[l], 0);
        normout<<<Bb * Nn, 256, 0, s2>>>(ah, al, gp, attl);
        cudaEventRecord(evJ[l], s2);

        // t1 = rowscale(attn_unnorm @ x)  (B = x row-major, trans-ldsm) -> qh
        mma_gemm<7,1><<<dim3(Nn / TM, Dd / TN, Bb), 256, SMEM_P1>>>(
            ah, xh, Nn, Dd, sA, sX, qh, nullptr, sX, Dd, nullptr, nullptr, gp);

        // fused: h = relu(t1@W0+b0); x = relu(h@W1+b1)+x0; q' = x@W2+b2 (or final)
        mlp3<<<dim3(BIGM / 64, 1, 1), 256, MLP_SMEM>>>(
            qh, W0h, b0, W1h, b1, gx, xh, th,
            W2h, b2, qh, out_x, last);
    }

    cudaStreamWaitEvent(0, evJ[Ll - 1], 0);
}

// round 14
// speedup vs baseline: 1.1456x; 1.1456x over previous
#include <cuda_runtime.h>
#include <cuda_fp16.h>
#include <cstdint>
#include <math.h>

#define Bb 64
#define Nn 512
#define Dd 256
#define Ll 4

// ======================= helpers =======================
__device__ __forceinline__ uint32_t smem_u32(const void* p) {
    uint32_t a;
    asm("{ .reg .u64 t; cvta.to.shared.u64 t, %1; cvt.u32.u64 %0, t; }" : "=r"(a) : "l"(p));
    return a;
}
__device__ __forceinline__ void cp16(uint32_t s, const void* g) {
    asm volatile("cp.async.cg.shared.global [%0], [%1], 16;" :: "r"(s), "l"(g));
}
__device__ __forceinline__ void ldsm4(uint32_t* r, uint32_t addr) {
    asm volatile("ldmatrix.sync.aligned.m8n8.x4.shared.b16 {%0,%1,%2,%3}, [%4];"
        : "=r"(r[0]), "=r"(r[1]), "=r"(r[2]), "=r"(r[3]) : "r"(addr));
}
__device__ __forceinline__ void ldsm4t(uint32_t* r, uint32_t addr) {
    asm volatile("ldmatrix.sync.aligned.m8n8.x4.trans.shared.b16 {%0,%1,%2,%3}, [%4];"
        : "=r"(r[0]), "=r"(r[1]), "=r"(r[2]), "=r"(r[3]) : "r"(addr));
}
__device__ __forceinline__ void mma16816(float* d, const uint32_t* a, const uint32_t* b) {
    asm volatile("mma.sync.aligned.m16n8k16.row.col.f32.f16.f16.f32 "
        "{%0,%1,%2,%3}, {%4,%5,%6,%7}, {%8,%9}, {%0,%1,%2,%3};"
        : "+f"(d[0]), "+f"(d[1]), "+f"(d[2]), "+f"(d[3])
        : "r"(a[0]), "r"(a[1]), "r"(a[2]), "r"(a[3]), "r"(b[0]), "r"(b[1]));
}

// ======================= device globals (scratch) =======================
#define XSZ (Bb * Nn * Dd)
#define ASZ (Bb * Nn * Nn)
__device__ __align__(128) __half g_xh[XSZ];
__device__ __align__(128) __half g_th[XSZ];              // lin0 output
__device__ __align__(128) __half g_qh[XSZ];              // q, then t1
__device__ __align__(128) __half g_ah[ASZ], g_al[ASZ];   // attn hi/lo (UNNORMALIZED)
__device__ __align__(128) __half g_wh[13 * Dd * Dd];
__device__ __align__(128) float g_x[XSZ];
__device__ __align__(128) float g_part[Bb * Nn * 4];     // row-sum partials (4 ctaY)

// ======================= MMA GEMM =======================
// BT=0: C = A[M,K] @ (Bh[Ncols,K])^T ; BT=1: C = A[M,K] @ (Bh[K,Ncols]) (trans-ldsm)
// EPI: 1=bias->h | 2=sigmoid*adj->hl + rowsum partials | 4=relu(bias)->h
//      5=relu(bias)+res->fp32+h | 6=bias->fp32 | 7=rowscale(1/sum part)->h
#define TM 128
#define TN 128
#define RS 80
#define RSB 272
#define MAT_BYTES (128 * RS)            // 10240
#define NSTG 3
#define SMEM_P1 (NSTG * 2 * MAT_BYTES)  // 61440

template<int EPI, int BT>
__global__ void __launch_bounds__(256, 2)
mma_gemm(const __half* __restrict__ Ah, const __half* __restrict__ Bh,
         int K, int ldb, long long sAz, long long sBz,
         float* __restrict__ Cf, __half* __restrict__ Ch, __half* __restrict__ Cl,
         long long sCz, int ldc,
         const float* __restrict__ bias, const float* __restrict__ res,
         const float* __restrict__ adj, float* __restrict__ part)
{
    // PDL: wait for the predecessor grid's writes before reading global memory.
    asm volatile("griddepcontrol.wait;" ::: "memory");

    extern __shared__ char smch[];
    const uint32_t sb = smem_u32(smch);
    const int tid = threadIdx.x;
    const int wid = tid >> 5;
    const int lane = tid & 31;
    const int z = blockIdx.z;
    const int bm = blockIdx.x * TM;
    const int bn = blockIdx.y * TN;

    Ah += (size_t)z * sAz + (size_t)bm * K;
    if (BT) Bh += (size_t)z * sBz + bn;
    else    Bh += (size_t)z * sBz + (size_t)bn * K;

    const int lr = tid >> 1;
    const int lc = (tid & 1) * 2;
    const uint32_t s_off = (uint32_t)lr * RS + (uint32_t)lc * 16;
    const int lrB = tid >> 3;
    const int lsB = tid & 7;

    auto issue = [&](int kb, int buf) {
        const size_t go = (size_t)lr * K + (size_t)kb * 32 + (size_t)lc * 8;
        const uint32_t s0 = sb + buf * (2 * MAT_BYTES) + s_off;
        cp16(s0,      Ah + go);
        cp16(s0 + 16, Ah + go + 8);
        if (BT) {
            const size_t gob = (size_t)(kb * 32 + lrB) * ldb + (size_t)lsB * 16;
            const uint32_t s0b = sb + buf * (2 * MAT_BYTES) + MAT_BYTES
                               + (uint32_t)lrB * RSB + (uint32_t)lsB * 32;
            cp16(s0b,      Bh + gob);
            cp16(s0b + 16, Bh + gob + 8);
        } else {
            const uint32_t s0b = sb + buf * (2 * MAT_BYTES) + MAT_BYTES + s_off;
            cp16(s0b,      Bh + go);
            cp16(s0b + 16, Bh + go + 8);
        }
    };

    const int KB = K / 32;
    issue(0, 0);
    asm volatile("cp.async.commit_group;" ::: "memory");
    issue(1, 1);
    asm volatile("cp.async.commit_group;" ::: "memory");

    // PDL: allow the next kernel's CTAs to become resident during our tail.
    asm volatile("griddepcontrol.launch_dependents;" ::: "memory");

    const int wm = (wid & 1) * 64;
    const int wn = (wid >> 1) * 32;

    float acc[4][4][4];
    #pragma unroll
    for (int i = 0; i < 4; i++)
        #pragma unroll
        for (int j = 0; j < 4; j++)
            #pragma unroll
            for (int k = 0; k < 4; k++) acc[i][j][k] = 0.0f;

    const int rr = lane & 15;
    const int csel = lane >> 4;
    const int gB = lane >> 3;
    const int rB = lane & 7;

    int bufC = 0, bufW = 2;
    for (int kb = 0; kb < KB; kb++) {
        asm volatile("cp.async.wait_group 1;" ::: "memory");
        __syncthreads();
        const uint32_t bufb = sb + bufC * (2 * MAT_BYTES);

        if (kb + 2 < KB) issue(kb + 2, bufW);
        asm volatile("cp.async.commit_group;" ::: "memory");

        #pragma unroll
        for (int ks = 0; ks < 2; ks++) {
            const uint32_t coff = (uint32_t)(ks * 2 + csel) * 16;
            uint32_t ah[4][4], bh[4][2];
            const uint32_t abase = bufb + (uint32_t)(wm + rr) * RS + coff;
            #pragma unroll
            for (int mt = 0; mt < 4; mt++)
                ldsm4(ah[mt], abase + mt * (16 * RS));
            if (BT) {
                const uint32_t btb = bufb + MAT_BYTES
                    + (uint32_t)(ks * 16 + (gB & 1) * 8 + rB) * RSB
                    + (uint32_t)(wn + (gB >> 1) * 8) * 2;
                #pragma unroll
                for (int ntt = 0; ntt < 2; ntt++) {
                    uint32_t t4[4];
                    ldsm4t(t4, btb + ntt * 32);
                    bh[2 * ntt][0] = t4[0]; bh[2 * ntt][1] = t4[1];
                    bh[2 * ntt + 1][0] = t4[2]; bh[2 * ntt + 1][1] = t4[3];
                }
            } else {
                const uint32_t bbase = bufb + MAT_BYTES + (uint32_t)(wn + rr) * RS + coff;
                #pragma unroll
                for (int ntt = 0; ntt < 2; ntt++) {
                    uint32_t t4[4];
                    ldsm4(t4, bbase + ntt * (16 * RS));
                    bh[2 * ntt][0] = t4[0]; bh[2 * ntt][1] = t4[2];
                    bh[2 * ntt + 1][0] = t4[1]; bh[2 * ntt + 1][1] = t4[3];
                }
            }
            #pragma unroll
            for (int mt = 0; mt < 4; mt++)
                #pragma unroll
                for (int nt = 0; nt < 4; nt++)
                    mma16816(acc[mt][nt], ah[mt], bh[nt]);
        }
        bufC = (bufC == NSTG - 1) ? 0 : bufC + 1;
        bufW = (bufW == NSTG - 1) ? 0 : bufW + 1;
    }

    // ======================= epilogue =======================
    const int qrow = lane >> 2;
    const int qcol = (lane & 3) * 2;
    float* redsm = (float*)smch;
    float rsum0[4], rsum1[4];

    #pragma unroll
    for (int mt = 0; mt < 4; mt++) {
        const int r0 = bm + wm + mt * 16 + qrow;
        const int r1 = r0 + 8;
        if (EPI == 2) { rsum0[mt] = 0.0f; rsum1[mt] = 0.0f; }
        #pragma unroll
        for (int nt = 0; nt < 4; nt++) {
            const int col = bn + wn + nt * 8 + qcol;
            float v00 = acc[mt][nt][0], v01 = acc[mt][nt][1];
            float v10 = acc[mt][nt][2], v11 = acc[mt][nt][3];

            if (EPI == 2) {
                const float* a0 = adj + ((size_t)z * Nn + r0) * Nn;
                const float* a1 = adj + ((size_t)z * Nn + r1) * Nn;
                float s00 = 1.0f / (1.0f + __expf(-v00));
                float s01 = 1.0f / (1.0f + __expf(-v01));
                float s10 = 1.0f / (1.0f + __expf(-v10));
                float s11 = 1.0f / (1.0f + __expf(-v11));
                v00 = (col == r0)     ? (s00 + 1e-5f) : s00 * __ldg(a0 + col);
                v01 = (col + 1 == r0) ? (s01 + 1e-5f) : s01 * __ldg(a0 + col + 1);
                v10 = (col == r1)     ? (s10 + 1e-5f) : s10 * __ldg(a1 + col);
                v11 = (col + 1 == r1) ? (s11 + 1e-5f) : s11 * __ldg(a1 + col + 1);
                rsum0[mt] += v00 + v01;
                rsum1[mt] += v10 + v11;
            } else if (EPI == 7) {
                const float4 p0 = *(const float4*)(part + ((size_t)z * Nn + r0) * 4);
                const float4 p1 = *(const float4*)(part + ((size_t)z * Nn + r1) * 4);
                const float inv0 = 1.0f / (p0.x + p0.y + p0.z + p0.w);
                const float inv1 = 1.0f / (p1.x + p1.y + p1.z + p1.w);
                v00 *= inv0; v01 *= inv0; v10 *= inv1; v11 *= inv1;
            } else if (EPI == 1) {
                const float b0v = __ldg(bias + col), b1v = __ldg(bias + col + 1);
                v00 += b0v; v01 += b1v; v10 += b0v; v11 += b1v;
            } else if (EPI == 4 || EPI == 5) {
                const float b0v = __ldg(bias + col), b1v = __ldg(bias + col + 1);
                v00 = fmaxf(v00 + b0v, 0.0f); v01 = fmaxf(v01 + b1v, 0.0f);
                v10 = fmaxf(v10 + b0v, 0.0f); v11 = fmaxf(v11 + b1v, 0.0f);
            }

            if (EPI == 6) {
                const float b0v = __ldg(bias + col), b1v = __ldg(bias + col + 1);
                float* cf0 = Cf + (size_t)z * sCz + (size_t)r0 * ldc;
                float* cf1 = Cf + (size_t)z * sCz + (size_t)r1 * ldc;
                float2 p0; p0.x = v00 + b0v; p0.y = v01 + b1v;
                float2 p1; p1.x = v10 + b0v; p1.y = v11 + b1v;
                *(float2*)(cf0 + col) = p0;
                *(float2*)(cf1 + col) = p1;
            } else {
                if (EPI == 5) {
                    const float* rp0 = res + (size_t)r0 * ldc;
                    const float* rp1 = res + (size_t)r1 * ldc;
                    v00 += rp0[col]; v01 += rp0[col + 1];
                    v10 += rp1[col]; v11 += rp1[col + 1];
                    float* cf0 = Cf + (size_t)r0 * ldc;
                    float* cf1 = Cf + (size_t)r1 * ldc;
                    float2 p0; p0.x = v00; p0.y = v01;
                    float2 p1; p1.x = v10; p1.y = v11;
                    *(float2*)(cf0 + col) = p0;
                    *(float2*)(cf1 + col) = p1;
                }
                __half* ch0 = Ch + (size_t)z * sCz + (size_t)r0 * ldc;
                __half* ch1 = Ch + (size_t)z * sCz + (size_t)r1 * ldc;
                const __half h00 = __float2half_rn(v00), h01 = __float2half_rn(v01);
                const __half h10 = __float2half_rn(v10), h11 = __float2half_rn(v11);
                __half2 hp0; hp0.x = h00; hp0.y = h01;
                __half2 hp1; hp1.x = h10; hp1.y = h11;
                *(__half2*)(ch0 + col) = hp0;
                *(__half2*)(ch1 + col) = hp1;
                if (EPI == 2) {
                    __half* cl0 = Cl + (size_t)z * sCz + (size_t)r0 * ldc;
                    __half* cl1 = Cl + (size_t)z * sCz + (size_t)r1 * ldc;
                    __half2 lp0, lp1;
                    lp0.x = __float2half_rn(v00 - __half2float(h00));
                    lp0.y = __float2half_rn(v01 - __half2float(h01));
                    lp1.x = __float2half_rn(v10 - __half2float(h10));
                    lp1.y = __float2half_rn(v11 - __half2float(h11));
                    *(__half2*)(cl0 + col) = lp0;
                    *(__half2*)(cl1 + col) = lp1;
                }
            }
        }
    }

    if (EPI == 2) {
        __syncthreads();
        const int nw = wid >> 1;
        #pragma unroll
        for (int mt = 0; mt < 4; mt++) {
            float s0 = rsum0[mt], s1 = rsum1[mt];
            s0 += __shfl_xor_sync(0xffffffffu, s0, 1);
            s0 += __shfl_xor_sync(0xffffffffu, s0, 2);
            s1 += __shfl_xor_sync(0xffffffffu, s1, 1);
            s1 += __shfl_xor_sync(0xffffffffu, s1, 2);
            if ((lane & 3) == 0) {
                const int rc = wm + mt * 16 + qrow;
                redsm[rc * 4 + nw]       = s0;
                redsm[(rc + 8) * 4 + nw] = s1;
            }
        }
        __syncthreads();
        if (tid < 128) {
            const float s = redsm[tid * 4] + redsm[tid * 4 + 1]
                          + redsm[tid * 4 + 2] + redsm[tid * 4 + 3];
            part[((size_t)z * Nn + bm + tid) * 4 + blockIdx.y] = s;
        }
    }
}

// ======================= small kernels =======================
__global__ void __launch_bounds__(256)
split_copy(const float4* __restrict__ src, float4* __restrict__ dst,
           __half* __restrict__ h, int n4)
{
    const int i = blockIdx.x * blockDim.x + threadIdx.x;
    if (i >= n4) return;
    const float4 v = src[i];
    dst[i] = v;
    __half2 a, b;
    a.x = __float2half_rn(v.x); a.y = __float2half_rn(v.y);
    b.x = __float2half_rn(v.z); b.y = __float2half_rn(v.w);
    *(__half2*)(h + 4 * (size_t)i) = a;
    *(__half2*)(h + 4 * (size_t)i + 2) = b;
}

__global__ void __launch_bounds__(256)
wconv(const float* __restrict__ src, __half* __restrict__ h, int n)
{
    const int i = blockIdx.x * blockDim.x + threadIdx.x;
    if (i < n) h[i] = __float2half_rn(src[i]);
}

// write normalized fp32 attn from unnormalized hi/lo + rowsum partials
__global__ void __launch_bounds__(256)
normout(const __half* __restrict__ h, const __half* __restrict__ l,
        const float* __restrict__ part, float* __restrict__ out)
{
    const size_t row = blockIdx.x;
    const float4 p = *(const float4*)(part + row * 4);
    const float inv = 1.0f / (p.x + p.y + p.z + p.w);
    const int t = threadIdx.x;
    const __half2 hv = *(const __half2*)(h + row * Nn + t * 2);
    const __half2 lv = *(const __half2*)(l + row * Nn + t * 2);
    float2 o;
    o.x = (__half2float(hv.x) + __half2float(lv.x)) * inv;
    o.y = (__half2float(hv.y) + __half2float(lv.y)) * inv;
    *(float2*)(out + row * Nn + t * 2) = o;
}

// ======================= launch =======================
extern "C" void kernel_launch(void* const* d_in, const int* in_sizes, int n_in,
                              void* d_out, int out_size)
{
    const float* x_in  = (const float*)d_in[0];
    const float* adj   = (const float*)d_in[1];
    const float* wA_w  = (const float*)d_in[2];
    const float* wA_b  = (const float*)d_in[3];
    const float* l0_w  = (const float*)d_in[4];
    const float* l0_b  = (const float*)d_in[5];
    const float* l1_w  = (const float*)d_in[6];
    const float* l1_b  = (const float*)d_in[7];
    const float* fin_w = (const float*)d_in[8];
    const float* fin_b = (const float*)d_in[9];

    float* out_x = (float*)d_out;
    float* attls = out_x + (size_t)Bb * Nn * Dd;

    __half *xh, *th, *qh, *ah, *al, *wh;
    float *gx, *gp;
    cudaGetSymbolAddress((void**)&xh, g_xh);
    cudaGetSymbolAddress((void**)&th, g_th);
    cudaGetSymbolAddress((void**)&qh, g_qh);
    cudaGetSymbolAddress((void**)&ah, g_ah); cudaGetSymbolAddress((void**)&al, g_al);
    cudaGetSymbolAddress((void**)&wh, g_wh);
    cudaGetSymbolAddress((void**)&gx, g_x);  cudaGetSymbolAddress((void**)&gp, g_part);

    static cudaStream_t s2 = nullptr;
    static cudaEvent_t evRoot, evW, evF[Ll], evJ[Ll];
    if (s2 == nullptr) {
        cudaStreamCreateWithFlags(&s2, cudaStreamNonBlocking);
        cudaEventCreateWithFlags(&evRoot, cudaEventDisableTiming);
        cudaEventCreateWithFlags(&evW, cudaEventDisableTiming);
        for (int l = 0; l < Ll; l++) {
            cudaEventCreateWithFlags(&evF[l], cudaEventDisableTiming);
            cudaEventCreateWithFlags(&evJ[l], cudaEventDisableTiming);
        }
    }

    cudaFuncSetAttribute(mma_gemm<1,0>, cudaFuncAttributeMaxDynamicSharedMemorySize, SMEM_P1);
    cudaFuncSetAttribute(mma_gemm<2,0>, cudaFuncAttributeMaxDynamicSharedMemorySize, SMEM_P1);
    cudaFuncSetAttribute(mma_gemm<4,0>, cudaFuncAttributeMaxDynamicSharedMemorySize, SMEM_P1);
    cudaFuncSetAttribute(mma_gemm<5,0>, cudaFuncAttributeMaxDynamicSharedMemorySize, SMEM_P1);
    cudaFuncSetAttribute(mma_gemm<6,0>, cudaFuncAttributeMaxDynamicSharedMemorySize, SMEM_P1);
    cudaFuncSetAttribute(mma_gemm<7,1>, cudaFuncAttributeMaxDynamicSharedMemorySize, SMEM_P1);

    const int WSZ = Dd * Dd;
    const long long sX = (long long)Nn * Dd;
    const long long sA = (long long)Nn * Nn;
    const long long LL0 = 0;
    float* FNULL = nullptr;
    __half* HNULL = nullptr;
    const float* CFNULL = nullptr;

    // PDL launch config for the serial GEMM chain on stream 0
    cudaLaunchAttribute pdlAttr;
    pdlAttr.id = cudaLaunchAttributeProgrammaticStreamSerialization;
    pdlAttr.val.programmaticStreamSerializationAllowed = 1;
    cudaLaunchConfig_t cfg = {};
    cfg.blockDim = dim3(256, 1, 1);
    cfg.dynamicSmemBytes = SMEM_P1;
    cfg.stream = 0;
    cfg.attrs = &pdlAttr;
    cfg.numAttrs = 1;

    // fork s2 at root: weight converts run concurrently with x split_copy
    cudaEventRecord(evRoot, 0);
    cudaStreamWaitEvent(s2, evRoot, 0);
    wconv<<<(4 * WSZ + 255) / 256, 256, 0, s2>>>(wA_w,  wh,            4 * WSZ);
    wconv<<<(4 * WSZ + 255) / 256, 256, 0, s2>>>(l0_w,  wh + 4 * WSZ,  4 * WSZ);
    wconv<<<(4 * WSZ + 255) / 256, 256, 0, s2>>>(l1_w,  wh + 8 * WSZ,  4 * WSZ);
    wconv<<<(WSZ + 255) / 256, 256, 0, s2>>>(fin_w, wh + 12 * WSZ, WSZ);
    cudaEventRecord(evW, s2);

    {
        const int n4 = XSZ / 4;
        split_copy<<<(n4 + 255) / 256, 256>>>((const float4*)x_in, (float4*)gx, xh, n4);
    }
    cudaStreamWaitEvent(0, evW, 0);

    const int BIGM = Bb * Nn;
    for (int l = 0; l < Ll; l++) {
        const float* ba = wA_b + (size_t)l * Dd;
        const float* b0 = l0_b + (size_t)l * Dd;
        const float* b1 = l1_b + (size_t)l * Dd;
        const __half* Wah = wh + (size_t)l * WSZ;
        const __half* W0h = wh + (size_t)(4 + l) * WSZ;
        const __half* W1h = wh + (size_t)(8 + l) * WSZ;
        float* attl = attls + (size_t)l * Bb * Nn * Nn;

        // q = x @ Wa^T + ba  ->  qh
        cfg.gridDim = dim3(BIGM / TM, Dd / TN, 1);
        cudaLaunchKernelEx(&cfg, mma_gemm<1,0>,
            (const __half*)xh, (const __half*)Wah, (int)Dd, 0, LL0, LL0,
            FNULL, qh, HNULL, LL0, (int)Dd, ba, CFNULL, CFNULL, FNULL);

        if (l > 0) cudaStreamWaitEvent(0, evJ[l - 1], 0);

        // attn_unnorm = sig(q @ x^T)*adj (+diag) -> ah/al + partials
        cfg.gridDim = dim3(Nn / TM, Nn / TN, Bb);
        cudaLaunchKernelEx(&cfg, mma_gemm<2,0>,
            (const __half*)qh, (const __half*)xh, (int)Dd, 0, sX, sX,
            FNULL, ah, al, sA, (int)Nn, CFNULL, CFNULL, adj, gp);

        cudaEventRecord(evF[l], 0);
        cudaStreamWaitEvent(s2, evF[l], 0);
        normout<<<Bb * Nn, 256, 0, s2>>>(ah, al, gp, attl);
        cudaEventRecord(evJ[l], s2);

        // t1 = rowscale(attn_unnorm @ x)  (B = x row-major, trans-ldsm) -> qh
        cfg.gridDim = dim3(Nn / TM, Dd / TN, Bb);
        cudaLaunchKernelEx(&cfg, mma_gemm<7,1>,
            (const __half*)ah, (const __half*)xh, (int)Nn, (int)Dd, sA, sX,
            FNULL, qh, HNULL, sX, (int)Dd, CFNULL, CFNULL, CFNULL, gp);

        // h = relu(t1 @ W0^T + b0) -> th
        cfg.gridDim = dim3(BIGM / TM, Dd / TN, 1);
        cudaLaunchKernelEx(&cfg, mma_gemm<4,0>,
            (const __half*)qh, (const __half*)W0h, (int)Dd, 0, LL0, LL0,
            FNULL, th, HNULL, LL0, (int)Dd, b0, CFNULL, CFNULL, FNULL);

        // x = relu(h @ W1^T + b1) + x0 -> g_x fp32 + xh
        cfg.gridDim = dim3(BIGM / TM, Dd / TN, 1);
        cudaLaunchKernelEx(&cfg, mma_gemm<5,0>,
            (const __half*)th, (const __half*)W1h, (int)Dd, 0, LL0, LL0,
            gx, xh, HNULL, LL0, (int)Dd, b1, (const float*)gx, CFNULL, FNULL);
    }

    cudaStreamWaitEvent(0, evJ[Ll - 1], 0);

    // out = x @ final^T + b
    cfg.gridDim = dim3(BIGM / TM, Dd / TN, 1);
    cudaLaunchKernelEx(&cfg, mma_gemm<6,0>,
        (const __half*)xh, (const __half*)(wh + 12 * WSZ), (int)Dd, 0, LL0, LL0,
        out_x, HNULL, HNULL, LL0, (int)Dd, fin_b, CFNULL, CFNULL, FNULL);
}